// round 2
// baseline (speedup 1.0000x reference)
#include <cuda_runtime.h>

// ---------------------------------------------------------------------------
// Tsit5 constants (float32, matching the jnp weak-typed f32 folding)
// ---------------------------------------------------------------------------
#define A21f 0.161f
#define A31f (-0.008480655492356989f)
#define A32f 0.335480655492357f
#define A41f 2.8971530571054935f
#define A42f (-6.359448489975075f)
#define A43f 4.3622954328695815f
#define A51f 5.325864828439257f
#define A52f (-11.748883564062828f)
#define A53f 7.4955393428898365f
#define A54f (-0.09249506636175525f)
#define A61f 5.86145544294642f
#define A62f (-12.92096931784711f)
#define A63f 8.159367898576159f
#define A64f (-0.071584973281401f)
#define A65f (-0.028269050394068383f)
#define B1f 0.09646076681806523f
#define B2f 0.01f
#define B3f 0.4798896504144996f
#define B4f 1.379008574103742f
#define B5f (-3.290069515436081f)
#define B6f 2.324710524099774f
#define E1f (-0.00178001105222577714f)
#define E2f (-0.0008164344596567469f)
#define E3f 0.007880878010261995f
#define E4f (-0.1447110071732629f)
#define E5f 0.5823571654525552f
#define E6f (-0.45808210592918697f)
#define E7f 0.015151515151515152f

#define RTOLf 1e-3f
#define ATOLf 1e-6f
#define DT0f  1e-3f

#define DDIM 64
#define HID  32
#define TRAJ_LEN 11
#define N_INTERVALS 10
#define MAX_INNER 64

#define WARPS_PER_BLOCK 4
#define THREADS_PER_BLOCK (WARPS_PER_BLOCK * 32)

// stable softplus == jnp.logaddexp(x, 0) = max(x,0) + log1p(exp(-|x|))
__device__ __forceinline__ float softplus_f(float x) {
    return fmaxf(x, 0.0f) + log1pf(expf(-fabsf(x)));
}

__global__ void __launch_bounds__(THREADS_PER_BLOCK, 2)
neural_ode_kernel(const float* __restrict__ x0s,
                  const float* __restrict__ W1, const float* __restrict__ b1,
                  const float* __restrict__ W2, const float* __restrict__ b2,
                  const float* __restrict__ W3, const float* __restrict__ b3,
                  const int* __restrict__ Tptr,
                  float* __restrict__ out, int B, int nIdx)
{
    const int lane = threadIdx.x & 31;
    const int wrp  = threadIdx.x >> 5;
    const int sys  = blockIdx.x * WARPS_PER_BLOCK + wrp;
    if (sys >= B) return;

    __shared__ __align__(16) float sv [WARPS_PER_BLOCK][DDIM]; // stage input vector
    __shared__ __align__(16) float sh1[WARPS_PER_BLOCK][HID];  // hidden 1
    __shared__ __align__(16) float sh2[WARPS_PER_BLOCK][HID];  // hidden 2

    float* svw  = sv [wrp];
    float* sh1w = sh1[wrp];
    float* sh2w = sh2[wrp];

    // ---- weights into registers (lane owns MLP output rows) ----
    float w1r[DDIM];
    #pragma unroll
    for (int j = 0; j < DDIM; ++j) w1r[j] = W1[lane * DDIM + j];
    float w2r[HID];
    #pragma unroll
    for (int j = 0; j < HID; ++j) w2r[j] = W2[lane * HID + j];
    float w3ar[HID], w3br[HID];
    #pragma unroll
    for (int j = 0; j < HID; ++j) {
        w3ar[j] = W3[lane * HID + j];
        w3br[j] = W3[(lane + 32) * HID + j];
    }
    const float b1r = b1[lane];
    const float b2r = b2[lane];
    const float b3l = b3[lane];
    const float b3h = b3[lane + 32];

    // f(z) -> k, fully inlined so weight arrays stay in registers
    auto evalf = [&](float zl, float zh, float& kl, float& kh) {
        svw[lane]      = zl;
        svw[lane + 32] = zh;
        __syncwarp();
        float a0 = 0.f, a1 = 0.f, a2 = 0.f, a3 = 0.f;
        const float4* v4 = (const float4*)svw;
        #pragma unroll
        for (int j = 0; j < DDIM / 4; ++j) {
            float4 v = v4[j];                       // broadcast LDS.128
            a0 = fmaf(w1r[4 * j + 0], v.x, a0);
            a1 = fmaf(w1r[4 * j + 1], v.y, a1);
            a2 = fmaf(w1r[4 * j + 2], v.z, a2);
            a3 = fmaf(w1r[4 * j + 3], v.w, a3);
        }
        float h1 = softplus_f(((a0 + a1) + (a2 + a3)) + b1r);
        sh1w[lane] = h1;
        __syncwarp();
        a0 = a1 = a2 = a3 = 0.f;
        const float4* h4 = (const float4*)sh1w;
        #pragma unroll
        for (int j = 0; j < HID / 4; ++j) {
            float4 v = h4[j];
            a0 = fmaf(w2r[4 * j + 0], v.x, a0);
            a1 = fmaf(w2r[4 * j + 1], v.y, a1);
            a2 = fmaf(w2r[4 * j + 2], v.z, a2);
            a3 = fmaf(w2r[4 * j + 3], v.w, a3);
        }
        float h2 = softplus_f(((a0 + a1) + (a2 + a3)) + b2r);
        sh2w[lane] = h2;
        __syncwarp();
        float c0 = 0.f, c1 = 0.f, c2 = 0.f, c3 = 0.f;
        float d0 = 0.f, d1 = 0.f, d2 = 0.f, d3 = 0.f;
        const float4* g4 = (const float4*)sh2w;
        #pragma unroll
        for (int j = 0; j < HID / 4; ++j) {
            float4 v = g4[j];
            c0 = fmaf(w3ar[4 * j + 0], v.x, c0);
            c1 = fmaf(w3ar[4 * j + 1], v.y, c1);
            c2 = fmaf(w3ar[4 * j + 2], v.z, c2);
            c3 = fmaf(w3ar[4 * j + 3], v.w, c3);
            d0 = fmaf(w3br[4 * j + 0], v.x, d0);
            d1 = fmaf(w3br[4 * j + 1], v.y, d1);
            d2 = fmaf(w3br[4 * j + 2], v.z, d2);
            d3 = fmaf(w3br[4 * j + 3], v.w, d3);
        }
        kl = ((c0 + c1) + (c2 + c3)) + b3l;
        kh = ((d0 + d1) + (d2 + d3)) + b3h;
        __syncwarp();   // protect shared buffers for the next call
    };

    // ---- state ----
    float y_lo = x0s[sys * DDIM + lane];
    float y_hi = x0s[sys * DDIM + 32 + lane];

    const int trajBase = sys * (TRAJ_LEN * DDIM);
    out[trajBase + lane]      = y_lo;   // ts[0] row
    out[trajBase + 32 + lane] = y_hi;

    const float Tf    = (float)(*Tptr);
    const float stepT = Tf / (float)N_INTERVALS;

    float t = 0.0f;
    float dt = DT0f;
    int   n  = 0;

    float k1l, k1h;
    evalf(y_lo, y_hi, k1l, k1h);   // FSAL seed; maintained thereafter

    for (int iv = 1; iv <= N_INTERVALS; ++iv) {
        const float t_target = (iv == N_INTERVALS) ? Tf : stepT * (float)iv;

        for (int it = 0; it < MAX_INNER; ++it) {
            float remaining = t_target - t;
            if (remaining <= 1e-12f) break;           // masked iterations are no-ops
            float h = fminf(dt, fmaxf(remaining, 0.0f));

            float k2l, k2h, k3l, k3h, k4l, k4h, k5l, k5h, k6l, k6h, k7l, k7h;
            float sl, sh_, zl, zh;

            // stage 2
            sl = A21f * k1l;                       sh_ = A21f * k1h;
            zl = fmaf(h, sl, y_lo);                zh = fmaf(h, sh_, y_hi);
            evalf(zl, zh, k2l, k2h);
            // stage 3
            sl = fmaf(A32f, k2l, A31f * k1l);      sh_ = fmaf(A32f, k2h, A31f * k1h);
            zl = fmaf(h, sl, y_lo);                zh = fmaf(h, sh_, y_hi);
            evalf(zl, zh, k3l, k3h);
            // stage 4
            sl = fmaf(A42f, k2l, A41f * k1l);      sh_ = fmaf(A42f, k2h, A41f * k1h);
            sl = fmaf(A43f, k3l, sl);              sh_ = fmaf(A43f, k3h, sh_);
            zl = fmaf(h, sl, y_lo);                zh = fmaf(h, sh_, y_hi);
            evalf(zl, zh, k4l, k4h);
            // stage 5
            sl = fmaf(A52f, k2l, A51f * k1l);      sh_ = fmaf(A52f, k2h, A51f * k1h);
            sl = fmaf(A53f, k3l, sl);              sh_ = fmaf(A53f, k3h, sh_);
            sl = fmaf(A54f, k4l, sl);              sh_ = fmaf(A54f, k4h, sh_);
            zl = fmaf(h, sl, y_lo);                zh = fmaf(h, sh_, y_hi);
            evalf(zl, zh, k5l, k5h);
            // stage 6
            sl = fmaf(A62f, k2l, A61f * k1l);      sh_ = fmaf(A62f, k2h, A61f * k1h);
            sl = fmaf(A63f, k3l, sl);              sh_ = fmaf(A63f, k3h, sh_);
            sl = fmaf(A64f, k4l, sl);              sh_ = fmaf(A64f, k4h, sh_);
            sl = fmaf(A65f, k5l, sl);              sh_ = fmaf(A65f, k5h, sh_);
            zl = fmaf(h, sl, y_lo);                zh = fmaf(h, sh_, y_hi);
            evalf(zl, zh, k6l, k6h);
            // y5
            sl = fmaf(B2f, k2l, B1f * k1l);        sh_ = fmaf(B2f, k2h, B1f * k1h);
            sl = fmaf(B3f, k3l, sl);               sh_ = fmaf(B3f, k3h, sh_);
            sl = fmaf(B4f, k4l, sl);               sh_ = fmaf(B4f, k4h, sh_);
            sl = fmaf(B5f, k5l, sl);               sh_ = fmaf(B5f, k5h, sh_);
            sl = fmaf(B6f, k6l, sl);               sh_ = fmaf(B6f, k6h, sh_);
            float y5l = fmaf(h, sl, y_lo);
            float y5h = fmaf(h, sh_, y_hi);
            // stage 7 (FSAL)
            evalf(y5l, y5h, k7l, k7h);
            // error estimate
            sl = fmaf(E2f, k2l, E1f * k1l);        sh_ = fmaf(E2f, k2h, E1f * k1h);
            sl = fmaf(E3f, k3l, sl);               sh_ = fmaf(E3f, k3h, sh_);
            sl = fmaf(E4f, k4l, sl);               sh_ = fmaf(E4f, k4h, sh_);
            sl = fmaf(E5f, k5l, sl);               sh_ = fmaf(E5f, k5h, sh_);
            sl = fmaf(E6f, k6l, sl);               sh_ = fmaf(E6f, k6h, sh_);
            sl = fmaf(E7f, k7l, sl);               sh_ = fmaf(E7f, k7h, sh_);
            float errl = h * sl;
            float errh = h * sh_;

            float scl = fmaf(RTOLf, fmaxf(fabsf(y_lo), fabsf(y5l)), ATOLf);
            float sch = fmaf(RTOLf, fmaxf(fabsf(y_hi), fabsf(y5h)), ATOLf);
            float ql = errl / scl;
            float qh = errh / sch;
            float local = ql * ql + qh * qh;
            #pragma unroll
            for (int o = 16; o > 0; o >>= 1)
                local += __shfl_xor_sync(0xffffffffu, local, o);

            float enorm = fmaxf(sqrtf(local * (1.0f / 64.0f)), 1e-10f);
            bool accept = (enorm <= 1.0f);
            float fac = 0.9f * powf(enorm, -0.2f);
            fac = fminf(fmaxf(fac, 0.1f), 5.0f);

            if (accept) {
                t = t + h;
                y_lo = y5l; y_hi = y5h;
                k1l = k7l;  k1h = k7h;   // FSAL: f(y_new) == k7, bitwise
            }
            dt = fmaxf(h * fac, 1e-8f);
            n += 1;
        }

        out[trajBase + iv * DDIM + lane]      = y_lo;
        out[trajBase + iv * DDIM + 32 + lane] = y_hi;
    }

    if (lane == 0)
        atomicAdd(&out[nIdx], (float)n);   // integer-valued, < 2^24 -> exact
}

// zero the (poisoned) tail of the output buffer that holds the step-count sum
__global__ void init_tail_kernel(float* __restrict__ out, int start, int total) {
    int i = start + blockIdx.x * blockDim.x + threadIdx.x;
    if (i < total) out[i] = 0.0f;
}

extern "C" void kernel_launch(void* const* d_in, const int* in_sizes, int n_in,
                              void* d_out, int out_size) {
    const float* x0s = (const float*)d_in[0];
    const float* W1  = (const float*)d_in[1];
    const float* b1  = (const float*)d_in[2];
    const float* W2  = (const float*)d_in[3];
    const float* b2  = (const float*)d_in[4];
    const float* W3  = (const float*)d_in[5];
    const float* b3  = (const float*)d_in[6];
    const int*   Tp  = (const int*)d_in[7];

    const int B = in_sizes[0] / DDIM;
    float* out = (float*)d_out;

    int trajElems = B * TRAJ_LEN * DDIM;
    if (trajElems >= out_size) trajElems = out_size - 1;  // safety
    const int nIdx = trajElems;

    // zero everything past the trajectories (n accumulator + any padding)
    const int tail = out_size - trajElems;
    init_tail_kernel<<<(tail + 255) / 256, 256>>>(out, trajElems, out_size);

    const int blocks = (B + WARPS_PER_BLOCK - 1) / WARPS_PER_BLOCK;
    neural_ode_kernel<<<blocks, THREADS_PER_BLOCK>>>(
        x0s, W1, b1, W2, b2, W3, b3, Tp, out, B, nIdx);
}

// round 4
// speedup vs baseline: 1.1237x; 1.1237x over previous
#include <cuda_runtime.h>

// ---------------------------------------------------------------------------
// Tsit5 constants (float32)
// ---------------------------------------------------------------------------
#define A21f 0.161f
#define A31f (-0.008480655492356989f)
#define A32f 0.335480655492357f
#define A41f 2.8971530571054935f
#define A42f (-6.359448489975075f)
#define A43f 4.3622954328695815f
#define A51f 5.325864828439257f
#define A52f (-11.748883564062828f)
#define A53f 7.4955393428898365f
#define A54f (-0.09249506636175525f)
#define A61f 5.86145544294642f
#define A62f (-12.92096931784711f)
#define A63f 8.159367898576159f
#define A64f (-0.071584973281401f)
#define A65f (-0.028269050394068383f)
#define B1f 0.09646076681806523f
#define B2f 0.01f
#define B3f 0.4798896504144996f
#define B4f 1.379008574103742f
#define B5f (-3.290069515436081f)
#define B6f 2.324710524099774f
#define E1f (-0.00178001105222577714f)
#define E2f (-0.0008164344596567469f)
#define E3f 0.007880878010261995f
#define E4f (-0.1447110071732629f)
#define E5f 0.5823571654525552f
#define E6f (-0.45808210592918697f)
#define E7f 0.015151515151515152f

#define RTOLf 1e-3f
#define ATOLf 1e-6f
#define DT0f  1e-3f

#define DDIM 64
#define HID  32
#define TRAJ_LEN 11
#define N_INTERVALS 10
#define MAX_INNER 64

#define WARPS_PER_BLOCK 4
#define THREADS_PER_BLOCK (WARPS_PER_BLOCK * 32)

// fast softplus: max(x,0) + log(1 + exp(-|x|)) with MUFU-based exp/log
__device__ __forceinline__ float softplus_f(float x) {
    return fmaxf(x, 0.0f) + __logf(1.0f + __expf(-fabsf(x)));
}

__global__ void __launch_bounds__(THREADS_PER_BLOCK, 2)
neural_ode_kernel(const float* __restrict__ x0s,
                  const float* __restrict__ W1, const float* __restrict__ b1,
                  const float* __restrict__ W2, const float* __restrict__ b2,
                  const float* __restrict__ W3, const float* __restrict__ b3,
                  const int* __restrict__ Tptr,
                  float* __restrict__ out, int B, int nIdx)
{
    const int lane = threadIdx.x & 31;
    const int wrp  = threadIdx.x >> 5;
    const int sys  = blockIdx.x * WARPS_PER_BLOCK + wrp;
    if (sys >= B) return;

    __shared__ __align__(16) float sv [WARPS_PER_BLOCK][DDIM]; // stage input vector
    __shared__ __align__(16) float sh1[WARPS_PER_BLOCK][HID];  // hidden 1
    __shared__ __align__(16) float sh2[WARPS_PER_BLOCK][HID];  // hidden 2

    float* svw  = sv [wrp];
    float* sh1w = sh1[wrp];
    float* sh2w = sh2[wrp];

    // ---- weights into registers (lane owns MLP output rows) ----
    float w1r[DDIM];
    #pragma unroll
    for (int j = 0; j < DDIM; ++j) w1r[j] = W1[lane * DDIM + j];
    float w2r[HID];
    #pragma unroll
    for (int j = 0; j < HID; ++j) w2r[j] = W2[lane * HID + j];
    float w3ar[HID], w3br[HID];
    #pragma unroll
    for (int j = 0; j < HID; ++j) {
        w3ar[j] = W3[lane * HID + j];
        w3br[j] = W3[(lane + 32) * HID + j];
    }
    const float b1r = b1[lane];
    const float b2r = b2[lane];
    const float b3l = b3[lane];
    const float b3h = b3[lane + 32];

    // f(z) -> k; 8-way accumulator ILP per matvec
    auto evalf = [&](float zl, float zh, float& kl, float& kh) {
        svw[lane]      = zl;
        svw[lane + 32] = zh;
        __syncwarp();
        float a0=0.f,a1=0.f,a2=0.f,a3=0.f,a4=0.f,a5=0.f,a6=0.f,a7=0.f;
        const float4* v4 = (const float4*)svw;
        #pragma unroll
        for (int j = 0; j < DDIM / 8; ++j) {
            float4 va = v4[2 * j];
            float4 vb = v4[2 * j + 1];
            a0 = fmaf(w1r[8 * j + 0], va.x, a0);
            a1 = fmaf(w1r[8 * j + 1], va.y, a1);
            a2 = fmaf(w1r[8 * j + 2], va.z, a2);
            a3 = fmaf(w1r[8 * j + 3], va.w, a3);
            a4 = fmaf(w1r[8 * j + 4], vb.x, a4);
            a5 = fmaf(w1r[8 * j + 5], vb.y, a5);
            a6 = fmaf(w1r[8 * j + 6], vb.z, a6);
            a7 = fmaf(w1r[8 * j + 7], vb.w, a7);
        }
        float h1 = softplus_f((((a0 + a4) + (a1 + a5)) + ((a2 + a6) + (a3 + a7))) + b1r);
        sh1w[lane] = h1;
        __syncwarp();
        a0=a1=a2=a3=a4=a5=a6=a7=0.f;
        const float4* h4 = (const float4*)sh1w;
        #pragma unroll
        for (int j = 0; j < HID / 8; ++j) {
            float4 va = h4[2 * j];
            float4 vb = h4[2 * j + 1];
            a0 = fmaf(w2r[8 * j + 0], va.x, a0);
            a1 = fmaf(w2r[8 * j + 1], va.y, a1);
            a2 = fmaf(w2r[8 * j + 2], va.z, a2);
            a3 = fmaf(w2r[8 * j + 3], va.w, a3);
            a4 = fmaf(w2r[8 * j + 4], vb.x, a4);
            a5 = fmaf(w2r[8 * j + 5], vb.y, a5);
            a6 = fmaf(w2r[8 * j + 6], vb.z, a6);
            a7 = fmaf(w2r[8 * j + 7], vb.w, a7);
        }
        float h2 = softplus_f((((a0 + a4) + (a1 + a5)) + ((a2 + a6) + (a3 + a7))) + b2r);
        sh2w[lane] = h2;
        __syncwarp();
        float c0=0.f,c1=0.f,c2=0.f,c3=0.f;
        float d0=0.f,d1=0.f,d2=0.f,d3=0.f;
        const float4* g4 = (const float4*)sh2w;
        #pragma unroll
        for (int j = 0; j < HID / 4; ++j) {
            float4 v = g4[j];
            c0 = fmaf(w3ar[4 * j + 0], v.x, c0);
            c1 = fmaf(w3ar[4 * j + 1], v.y, c1);
            c2 = fmaf(w3ar[4 * j + 2], v.z, c2);
            c3 = fmaf(w3ar[4 * j + 3], v.w, c3);
            d0 = fmaf(w3br[4 * j + 0], v.x, d0);
            d1 = fmaf(w3br[4 * j + 1], v.y, d1);
            d2 = fmaf(w3br[4 * j + 2], v.z, d2);
            d3 = fmaf(w3br[4 * j + 3], v.w, d3);
        }
        kl = ((c0 + c1) + (c2 + c3)) + b3l;
        kh = ((d0 + d1) + (d2 + d3)) + b3h;
        __syncwarp();   // protect shared buffers for the next call
    };

    // ---- state ----
    float y_lo = x0s[sys * DDIM + lane];
    float y_hi = x0s[sys * DDIM + 32 + lane];

    const int trajBase = sys * (TRAJ_LEN * DDIM);
    out[trajBase + lane]      = y_lo;   // ts[0] row
    out[trajBase + 32 + lane] = y_hi;

    const float Tf    = (float)(*Tptr);
    const float stepT = Tf / (float)N_INTERVALS;

    float t = 0.0f;
    float dt = DT0f;
    int   n  = 0;

    float k1l, k1h;
    evalf(y_lo, y_hi, k1l, k1h);   // FSAL seed; maintained thereafter

    for (int iv = 1; iv <= N_INTERVALS; ++iv) {
        const float t_target = (iv == N_INTERVALS) ? Tf : stepT * (float)iv;

        for (int it = 0; it < MAX_INNER; ++it) {
            float remaining = t_target - t;
            if (remaining <= 1e-12f) break;           // masked iterations are no-ops
            float h = fminf(dt, fmaxf(remaining, 0.0f));

            float k2l, k2h, k3l, k3h, k4l, k4h, k5l, k5h, k6l, k6h, k7l, k7h;
            float sl, sh_, zl, zh;

            // stage 2
            sl = A21f * k1l;                       sh_ = A21f * k1h;
            zl = fmaf(h, sl, y_lo);                zh = fmaf(h, sh_, y_hi);
            evalf(zl, zh, k2l, k2h);
            // stage 3
            sl = fmaf(A32f, k2l, A31f * k1l);      sh_ = fmaf(A32f, k2h, A31f * k1h);
            zl = fmaf(h, sl, y_lo);                zh = fmaf(h, sh_, y_hi);
            evalf(zl, zh, k3l, k3h);
            // stage 4
            sl = fmaf(A42f, k2l, A41f * k1l);      sh_ = fmaf(A42f, k2h, A41f * k1h);
            sl = fmaf(A43f, k3l, sl);              sh_ = fmaf(A43f, k3h, sh_);
            zl = fmaf(h, sl, y_lo);                zh = fmaf(h, sh_, y_hi);
            evalf(zl, zh, k4l, k4h);
            // stage 5
            sl = fmaf(A52f, k2l, A51f * k1l);      sh_ = fmaf(A52f, k2h, A51f * k1h);
            sl = fmaf(A53f, k3l, sl);              sh_ = fmaf(A53f, k3h, sh_);
            sl = fmaf(A54f, k4l, sl);              sh_ = fmaf(A54f, k4h, sh_);
            zl = fmaf(h, sl, y_lo);                zh = fmaf(h, sh_, y_hi);
            evalf(zl, zh, k5l, k5h);
            // stage 6
            sl = fmaf(A62f, k2l, A61f * k1l);      sh_ = fmaf(A62f, k2h, A61f * k1h);
            sl = fmaf(A63f, k3l, sl);              sh_ = fmaf(A63f, k3h, sh_);
            sl = fmaf(A64f, k4l, sl);              sh_ = fmaf(A64f, k4h, sh_);
            sl = fmaf(A65f, k5l, sl);              sh_ = fmaf(A65f, k5h, sh_);
            zl = fmaf(h, sl, y_lo);                zh = fmaf(h, sh_, y_hi);
            evalf(zl, zh, k6l, k6h);
            // y5
            sl = fmaf(B2f, k2l, B1f * k1l);        sh_ = fmaf(B2f, k2h, B1f * k1h);
            sl = fmaf(B3f, k3l, sl);               sh_ = fmaf(B3f, k3h, sh_);
            sl = fmaf(B4f, k4l, sl);               sh_ = fmaf(B4f, k4h, sh_);
            sl = fmaf(B5f, k5l, sl);               sh_ = fmaf(B5f, k5h, sh_);
            sl = fmaf(B6f, k6l, sl);               sh_ = fmaf(B6f, k6h, sh_);
            float y5l = fmaf(h, sl, y_lo);
            float y5h = fmaf(h, sh_, y_hi);
            // stage 7 (FSAL)
            evalf(y5l, y5h, k7l, k7h);
            // error estimate
            sl = fmaf(E2f, k2l, E1f * k1l);        sh_ = fmaf(E2f, k2h, E1f * k1h);
            sl = fmaf(E3f, k3l, sl);               sh_ = fmaf(E3f, k3h, sh_);
            sl = fmaf(E4f, k4l, sl);               sh_ = fmaf(E4f, k4h, sh_);
            sl = fmaf(E5f, k5l, sl);               sh_ = fmaf(E5f, k5h, sh_);
            sl = fmaf(E6f, k6l, sl);               sh_ = fmaf(E6f, k6h, sh_);
            sl = fmaf(E7f, k7l, sl);               sh_ = fmaf(E7f, k7h, sh_);
            float errl = h * sl;
            float errh = h * sh_;

            float scl = fmaf(RTOLf, fmaxf(fabsf(y_lo), fabsf(y5l)), ATOLf);
            float sch = fmaf(RTOLf, fmaxf(fabsf(y_hi), fabsf(y5h)), ATOLf);
            float ql = __fdividef(errl, scl);
            float qh = __fdividef(errh, sch);
            float local = ql * ql + qh * qh;
            #pragma unroll
            for (int o = 16; o > 0; o >>= 1)
                local += __shfl_xor_sync(0xffffffffu, local, o);

            float enorm = fmaxf(sqrtf(local * (1.0f / 64.0f)), 1e-10f);
            bool accept = (enorm <= 1.0f);
            float fac = 0.9f * exp2f(-0.2f * __log2f(enorm));
            fac = fminf(fmaxf(fac, 0.1f), 5.0f);

            if (accept) {
                t = t + h;
                y_lo = y5l; y_hi = y5h;
                k1l = k7l;  k1h = k7h;   // FSAL: f(y_new) == k7
            }
            dt = fmaxf(h * fac, 1e-8f);
            n += 1;
        }

        out[trajBase + iv * DDIM + lane]      = y_lo;
        out[trajBase + iv * DDIM + 32 + lane] = y_hi;
    }

    if (lane == 0)
        atomicAdd(&out[nIdx], (float)n);   // integer-valued, < 2^24 -> exact
}

// zero the (poisoned) tail of the output buffer that holds the step-count sum
__global__ void init_tail_kernel(float* __restrict__ out, int start, int total) {
    int i = start + blockIdx.x * blockDim.x + threadIdx.x;
    if (i < total) out[i] = 0.0f;
}

extern "C" void kernel_launch(void* const* d_in, const int* in_sizes, int n_in,
                              void* d_out, int out_size) {
    const float* x0s = (const float*)d_in[0];
    const float* W1  = (const float*)d_in[1];
    const float* b1  = (const float*)d_in[2];
    const float* W2  = (const float*)d_in[3];
    const float* b2  = (const float*)d_in[4];
    const float* W3  = (const float*)d_in[5];
    const float* b3  = (const float*)d_in[6];
    const int*   Tp  = (const int*)d_in[7];

    const int B = in_sizes[0] / DDIM;
    float* out = (float*)d_out;

    int trajElems = B * TRAJ_LEN * DDIM;
    if (trajElems >= out_size) trajElems = out_size - 1;  // safety
    const int nIdx = trajElems;

    // zero everything past the trajectories (n accumulator + any padding)
    const int tail = out_size - trajElems;
    init_tail_kernel<<<(tail + 255) / 256, 256>>>(out, trajElems, out_size);

    const int blocks = (B + WARPS_PER_BLOCK - 1) / WARPS_PER_BLOCK;
    neural_ode_kernel<<<blocks, THREADS_PER_BLOCK>>>(
        x0s, W1, b1, W2, b2, W3, b3, Tp, out, B, nIdx);
}

// round 5
// speedup vs baseline: 1.2941x; 1.1516x over previous
#include <cuda_runtime.h>

typedef unsigned long long u64;

// ---------------------------------------------------------------------------
// packed f32x2 helpers (Blackwell FFMA2 path)
// ---------------------------------------------------------------------------
__device__ __forceinline__ u64 ffma2(u64 a, u64 b, u64 c) {
    u64 d; asm("fma.rn.f32x2 %0, %1, %2, %3;" : "=l"(d) : "l"(a), "l"(b), "l"(c)); return d;
}
__device__ __forceinline__ u64 fadd2(u64 a, u64 b) {
    u64 d; asm("add.rn.f32x2 %0, %1, %2;" : "=l"(d) : "l"(a), "l"(b)); return d;
}
__device__ __forceinline__ u64 fmul2(u64 a, u64 b) {
    u64 d; asm("mul.rn.f32x2 %0, %1, %2;" : "=l"(d) : "l"(a), "l"(b)); return d;
}
__device__ __forceinline__ u64 pack2(float lo, float hi) {
    u64 d; asm("mov.b64 %0, {%1, %2};" : "=l"(d) : "f"(lo), "f"(hi)); return d;
}
__device__ __forceinline__ float2 unpk(u64 v) {
    float2 r; asm("mov.b64 {%0, %1}, %2;" : "=f"(r.x), "=f"(r.y) : "l"(v)); return r;
}
__device__ __forceinline__ u64 dup2(float c) { return pack2(c, c); }

// ---------------------------------------------------------------------------
// Tsit5 constants
// ---------------------------------------------------------------------------
#define A21f 0.161f
#define A31f (-0.008480655492356989f)
#define A32f 0.335480655492357f
#define A41f 2.8971530571054935f
#define A42f (-6.359448489975075f)
#define A43f 4.3622954328695815f
#define A51f 5.325864828439257f
#define A52f (-11.748883564062828f)
#define A53f 7.4955393428898365f
#define A54f (-0.09249506636175525f)
#define A61f 5.86145544294642f
#define A62f (-12.92096931784711f)
#define A63f 8.159367898576159f
#define A64f (-0.071584973281401f)
#define A65f (-0.028269050394068383f)
#define B1f 0.09646076681806523f
#define B2f 0.01f
#define B3f 0.4798896504144996f
#define B4f 1.379008574103742f
#define B5f (-3.290069515436081f)
#define B6f 2.324710524099774f
#define E1f (-0.00178001105222577714f)
#define E2f (-0.0008164344596567469f)
#define E3f 0.007880878010261995f
#define E4f (-0.1447110071732629f)
#define E5f 0.5823571654525552f
#define E6f (-0.45808210592918697f)
#define E7f 0.015151515151515152f

#define RTOLf 1e-3f
#define ATOLf 1e-6f
#define DT0f  1e-3f

#define DDIM 64
#define HID  32
#define TRAJ_LEN 11
#define N_INTERVALS 10
#define MAX_INNER 64

#define WARPS_PER_BLOCK 4
#define THREADS_PER_BLOCK (WARPS_PER_BLOCK * 32)

// fast softplus: max(x,0) + log(1 + exp(-|x|)) with MUFU exp/log
__device__ __forceinline__ float softplus_f(float x) {
    return fmaxf(x, 0.0f) + __logf(1.0f + __expf(-fabsf(x)));
}

__global__ void __launch_bounds__(THREADS_PER_BLOCK, 2)
neural_ode_kernel(const float* __restrict__ x0s,
                  const float* __restrict__ W1, const float* __restrict__ b1,
                  const float* __restrict__ W2, const float* __restrict__ b2,
                  const float* __restrict__ W3, const float* __restrict__ b3,
                  const int* __restrict__ Tptr,
                  float* __restrict__ out, int B, int nIdx)
{
    const int lane = threadIdx.x & 31;
    const int wrp  = threadIdx.x >> 5;
    const int sys  = blockIdx.x * WARPS_PER_BLOCK + wrp;
    if (sys >= B) return;

    __shared__ __align__(16) float sv [WARPS_PER_BLOCK][DDIM]; // stage input vector
    __shared__ __align__(16) float sh1[WARPS_PER_BLOCK][HID];  // hidden 1
    __shared__ __align__(16) float sh2[WARPS_PER_BLOCK][HID];  // hidden 2

    float* svw  = sv [wrp];
    float* sh1w = sh1[wrp];
    float* sh2w = sh2[wrp];

    // ---- weights into registers, packed as f32x2 pairs ----
    // layer1: lane owns hidden unit `lane`; pairs over input coords
    u64 w1p[DDIM / 2];
    {
        const float2* r = (const float2*)(W1 + lane * DDIM);
        #pragma unroll
        for (int j = 0; j < DDIM / 2; ++j) { float2 v = r[j]; w1p[j] = pack2(v.x, v.y); }
    }
    u64 w2p[HID / 2];
    {
        const float2* r = (const float2*)(W2 + lane * HID);
        #pragma unroll
        for (int j = 0; j < HID / 2; ++j) { float2 v = r[j]; w2p[j] = pack2(v.x, v.y); }
    }
    // layer3: lane owns output coords (2*lane, 2*lane+1)
    u64 w3ap[HID / 2], w3bp[HID / 2];
    {
        const float2* ra = (const float2*)(W3 + (2 * lane) * HID);
        const float2* rb = (const float2*)(W3 + (2 * lane + 1) * HID);
        #pragma unroll
        for (int j = 0; j < HID / 2; ++j) {
            float2 va = ra[j]; w3ap[j] = pack2(va.x, va.y);
            float2 vb = rb[j]; w3bp[j] = pack2(vb.x, vb.y);
        }
    }
    const float b1r = b1[lane];
    const float b2r = b2[lane];
    const float2 b3v = ((const float2*)b3)[lane];   // (row 2*lane, row 2*lane+1)

    // f(z) -> k, packed pairs: z/k hold coords (2*lane, 2*lane+1)
    auto evalf = [&](u64 z) -> u64 {
        *(u64*)&svw[2 * lane] = z;              // STS.64
        __syncwarp();
        // ---- layer 1: 64 inputs = 32 pairs, 8 packed accumulators ----
        u64 a0=0,a1=0,a2=0,a3=0,a4=0,a5=0,a6=0,a7=0;
        const ulonglong2* vv = (const ulonglong2*)svw;   // 16 x 16B
        #pragma unroll
        for (int j = 0; j < 4; ++j) {
            ulonglong2 p0 = vv[4 * j + 0];
            ulonglong2 p1 = vv[4 * j + 1];
            ulonglong2 p2 = vv[4 * j + 2];
            ulonglong2 p3 = vv[4 * j + 3];
            a0 = ffma2(w1p[8 * j + 0], p0.x, a0);
            a1 = ffma2(w1p[8 * j + 1], p0.y, a1);
            a2 = ffma2(w1p[8 * j + 2], p1.x, a2);
            a3 = ffma2(w1p[8 * j + 3], p1.y, a3);
            a4 = ffma2(w1p[8 * j + 4], p2.x, a4);
            a5 = ffma2(w1p[8 * j + 5], p2.y, a5);
            a6 = ffma2(w1p[8 * j + 6], p3.x, a6);
            a7 = ffma2(w1p[8 * j + 7], p3.y, a7);
        }
        u64 s01 = fadd2(fadd2(a0, a1), fadd2(a2, a3));
        u64 s23 = fadd2(fadd2(a4, a5), fadd2(a6, a7));
        float2 sa = unpk(fadd2(s01, s23));
        float h1 = softplus_f((sa.x + sa.y) + b1r);
        sh1w[lane] = h1;
        __syncwarp();
        // ---- layer 2: 32 inputs = 16 pairs, 4 packed accumulators ----
        u64 c0=0,c1=0,c2=0,c3=0;
        const ulonglong2* hh = (const ulonglong2*)sh1w;  // 8 x 16B
        #pragma unroll
        for (int j = 0; j < 4; ++j) {
            ulonglong2 p0 = hh[2 * j + 0];
            ulonglong2 p1 = hh[2 * j + 1];
            c0 = ffma2(w2p[4 * j + 0], p0.x, c0);
            c1 = ffma2(w2p[4 * j + 1], p0.y, c1);
            c2 = ffma2(w2p[4 * j + 2], p1.x, c2);
            c3 = ffma2(w2p[4 * j + 3], p1.y, c3);
        }
        float2 sb = unpk(fadd2(fadd2(c0, c1), fadd2(c2, c3)));
        float h2 = softplus_f((sb.x + sb.y) + b2r);
        sh2w[lane] = h2;
        __syncwarp();
        // ---- layer 3: two output rows, shared input pairs ----
        u64 e0=0,e1=0,e2=0,e3=0;   // row 2*lane
        u64 f0=0,f1=0,f2=0,f3=0;   // row 2*lane+1
        const ulonglong2* gg = (const ulonglong2*)sh2w;  // 8 x 16B
        #pragma unroll
        for (int j = 0; j < 4; ++j) {
            ulonglong2 p0 = gg[2 * j + 0];
            ulonglong2 p1 = gg[2 * j + 1];
            e0 = ffma2(w3ap[4 * j + 0], p0.x, e0);
            f0 = ffma2(w3bp[4 * j + 0], p0.x, f0);
            e1 = ffma2(w3ap[4 * j + 1], p0.y, e1);
            f1 = ffma2(w3bp[4 * j + 1], p0.y, f1);
            e2 = ffma2(w3ap[4 * j + 2], p1.x, e2);
            f2 = ffma2(w3bp[4 * j + 2], p1.x, f2);
            e3 = ffma2(w3ap[4 * j + 3], p1.y, e3);
            f3 = ffma2(w3bp[4 * j + 3], p1.y, f3);
        }
        float2 se = unpk(fadd2(fadd2(e0, e1), fadd2(e2, e3)));
        float2 sf = unpk(fadd2(fadd2(f0, f1), fadd2(f2, f3)));
        // no trailing syncwarp: next call's barriers cover the WAR hazards
        return pack2((se.x + se.y) + b3v.x, (sf.x + sf.y) + b3v.y);
    };

    // ---- state (packed: coords 2*lane, 2*lane+1) ----
    float2 x0v = ((const float2*)x0s)[sys * (DDIM / 2) + lane];
    u64 yp = pack2(x0v.x, x0v.y);

    const int trajBase = sys * (TRAJ_LEN * DDIM);
    ((float2*)out)[(trajBase >> 1) + lane] = x0v;    // ts[0] row

    const float Tf    = (float)(*Tptr);
    const float stepT = Tf / (float)N_INTERVALS;

    float t = 0.0f;
    float dt = DT0f;
    int   n  = 0;

    u64 k1p = evalf(yp);   // FSAL seed

    for (int iv = 1; iv <= N_INTERVALS; ++iv) {
        const float t_target = (iv == N_INTERVALS) ? Tf : stepT * (float)iv;

        for (int it = 0; it < MAX_INNER; ++it) {
            float remaining = t_target - t;
            if (remaining <= 1e-12f) break;
            float h = fminf(dt, fmaxf(remaining, 0.0f));
            u64 hp = dup2(h);

            // stage 2
            u64 s = fmul2(dup2(A21f), k1p);
            u64 k2p = evalf(ffma2(hp, s, yp));
            // stage 3
            s = ffma2(dup2(A32f), k2p, fmul2(dup2(A31f), k1p));
            u64 k3p = evalf(ffma2(hp, s, yp));
            // stage 4
            s = ffma2(dup2(A42f), k2p, fmul2(dup2(A41f), k1p));
            s = ffma2(dup2(A43f), k3p, s);
            u64 k4p = evalf(ffma2(hp, s, yp));
            // stage 5
            s = ffma2(dup2(A52f), k2p, fmul2(dup2(A51f), k1p));
            s = ffma2(dup2(A53f), k3p, s);
            s = ffma2(dup2(A54f), k4p, s);
            u64 k5p = evalf(ffma2(hp, s, yp));
            // stage 6
            s = ffma2(dup2(A62f), k2p, fmul2(dup2(A61f), k1p));
            s = ffma2(dup2(A63f), k3p, s);
            s = ffma2(dup2(A64f), k4p, s);
            s = ffma2(dup2(A65f), k5p, s);
            u64 k6p = evalf(ffma2(hp, s, yp));
            // y5
            s = ffma2(dup2(B2f), k2p, fmul2(dup2(B1f), k1p));
            s = ffma2(dup2(B3f), k3p, s);
            s = ffma2(dup2(B4f), k4p, s);
            s = ffma2(dup2(B5f), k5p, s);
            s = ffma2(dup2(B6f), k6p, s);
            u64 y5p = ffma2(hp, s, yp);
            // stage 7 (FSAL)
            u64 k7p = evalf(y5p);
            // error estimate
            s = ffma2(dup2(E2f), k2p, fmul2(dup2(E1f), k1p));
            s = ffma2(dup2(E3f), k3p, s);
            s = ffma2(dup2(E4f), k4p, s);
            s = ffma2(dup2(E5f), k5p, s);
            s = ffma2(dup2(E6f), k6p, s);
            s = ffma2(dup2(E7f), k7p, s);
            float2 ev  = unpk(fmul2(hp, s));
            float2 yv  = unpk(yp);
            float2 y5v = unpk(y5p);

            float scl = fmaf(RTOLf, fmaxf(fabsf(yv.x), fabsf(y5v.x)), ATOLf);
            float sch = fmaf(RTOLf, fmaxf(fabsf(yv.y), fabsf(y5v.y)), ATOLf);
            float ql = __fdividef(ev.x, scl);
            float qh = __fdividef(ev.y, sch);
            float local = ql * ql + qh * qh;
            #pragma unroll
            for (int o = 16; o > 0; o >>= 1)
                local += __shfl_xor_sync(0xffffffffu, local, o);

            float enorm = fmaxf(sqrtf(local * (1.0f / 64.0f)), 1e-10f);
            bool accept = (enorm <= 1.0f);
            float fac = 0.9f * exp2f(-0.2f * __log2f(enorm));
            fac = fminf(fmaxf(fac, 0.1f), 5.0f);

            if (accept) {
                t = t + h;
                yp  = y5p;
                k1p = k7p;   // FSAL
            }
            dt = fmaxf(h * fac, 1e-8f);
            n += 1;
        }

        float2 yv = unpk(yp);
        ((float2*)out)[((trajBase + iv * DDIM) >> 1) + lane] = yv;
    }

    if (lane == 0)
        atomicAdd(&out[nIdx], (float)n);   // integer-valued, exact
}

// zero the (poisoned) tail of the output buffer that holds the step-count sum
__global__ void init_tail_kernel(float* __restrict__ out, int start, int total) {
    int i = start + blockIdx.x * blockDim.x + threadIdx.x;
    if (i < total) out[i] = 0.0f;
}

extern "C" void kernel_launch(void* const* d_in, const int* in_sizes, int n_in,
                              void* d_out, int out_size) {
    const float* x0s = (const float*)d_in[0];
    const float* W1  = (const float*)d_in[1];
    const float* b1  = (const float*)d_in[2];
    const float* W2  = (const float*)d_in[3];
    const float* b2  = (const float*)d_in[4];
    const float* W3  = (const float*)d_in[5];
    const float* b3  = (const float*)d_in[6];
    const int*   Tp  = (const int*)d_in[7];

    const int B = in_sizes[0] / DDIM;
    float* out = (float*)d_out;

    int trajElems = B * TRAJ_LEN * DDIM;
    if (trajElems >= out_size) trajElems = out_size - 1;  // safety
    const int nIdx = trajElems;

    const int tail = out_size - trajElems;
    init_tail_kernel<<<(tail + 255) / 256, 256>>>(out, trajElems, out_size);

    const int blocks = (B + WARPS_PER_BLOCK - 1) / WARPS_PER_BLOCK;
    neural_ode_kernel<<<blocks, THREADS_PER_BLOCK>>>(
        x0s, W1, b1, W2, b2, W3, b3, Tp, out, B, nIdx);
}

// round 9
// speedup vs baseline: 1.3520x; 1.0448x over previous
#include <cuda_runtime.h>

typedef unsigned long long u64;

// ---------------------------------------------------------------------------
// packed f32x2 helpers (Blackwell FFMA2 path)
// ---------------------------------------------------------------------------
__device__ __forceinline__ u64 ffma2(u64 a, u64 b, u64 c) {
    u64 d; asm("fma.rn.f32x2 %0, %1, %2, %3;" : "=l"(d) : "l"(a), "l"(b), "l"(c)); return d;
}
__device__ __forceinline__ u64 fadd2(u64 a, u64 b) {
    u64 d; asm("add.rn.f32x2 %0, %1, %2;" : "=l"(d) : "l"(a), "l"(b)); return d;
}
__device__ __forceinline__ u64 fmul2(u64 a, u64 b) {
    u64 d; asm("mul.rn.f32x2 %0, %1, %2;" : "=l"(d) : "l"(a), "l"(b)); return d;
}
__device__ __forceinline__ u64 pack2(float lo, float hi) {
    u64 d; asm("mov.b64 %0, {%1, %2};" : "=l"(d) : "f"(lo), "f"(hi)); return d;
}
__device__ __forceinline__ float2 unpk(u64 v) {
    float2 r; asm("mov.b64 {%0, %1}, %2;" : "=f"(r.x), "=f"(r.y) : "l"(v)); return r;
}
__device__ __forceinline__ u64 dup2(float c) { return pack2(c, c); }

// ---------------------------------------------------------------------------
// Tsit5 constants
// ---------------------------------------------------------------------------
#define A21f 0.161f
#define A31f (-0.008480655492356989f)
#define A32f 0.335480655492357f
#define A41f 2.8971530571054935f
#define A42f (-6.359448489975075f)
#define A43f 4.3622954328695815f
#define A51f 5.325864828439257f
#define A52f (-11.748883564062828f)
#define A53f 7.4955393428898365f
#define A54f (-0.09249506636175525f)
#define A61f 5.86145544294642f
#define A62f (-12.92096931784711f)
#define A63f 8.159367898576159f
#define A64f (-0.071584973281401f)
#define A65f (-0.028269050394068383f)
#define B1f 0.09646076681806523f
#define B2f 0.01f
#define B3f 0.4798896504144996f
#define B4f 1.379008574103742f
#define B5f (-3.290069515436081f)
#define B6f 2.324710524099774f
#define E1f (-0.00178001105222577714f)
#define E2f (-0.0008164344596567469f)
#define E3f 0.007880878010261995f
#define E4f (-0.1447110071732629f)
#define E5f 0.5823571654525552f
#define E6f (-0.45808210592918697f)
#define E7f 0.015151515151515152f

#define RTOLf 1e-3f
#define ATOLf 1e-6f
#define DT0f  1e-3f

#define DDIM 64
#define HID  32
#define TRAJ_LEN 11
#define N_INTERVALS 10
#define MAX_INNER 64

#define WARPS_PER_BLOCK 4
#define THREADS_PER_BLOCK (WARPS_PER_BLOCK * 32)

// fast softplus: max(x,0) + log(1 + exp(-|x|)) with MUFU exp/log
__device__ __forceinline__ float softplus_f(float x) {
    return fmaxf(x, 0.0f) + __logf(1.0f + __expf(-fabsf(x)));
}

__global__ void __launch_bounds__(THREADS_PER_BLOCK, 2)
neural_ode_kernel(const float* __restrict__ x0s,
                  const float* __restrict__ W1, const float* __restrict__ b1,
                  const float* __restrict__ W2, const float* __restrict__ b2,
                  const float* __restrict__ W3, const float* __restrict__ b3,
                  const int* __restrict__ Tptr,
                  float* __restrict__ out, int B, int nIdx)
{
    const int lane = threadIdx.x & 31;
    const int wrp  = threadIdx.x >> 5;
    const int sys  = blockIdx.x * WARPS_PER_BLOCK + wrp;
    if (sys >= B) return;

    const int g = lane >> 4;     // input-half group (0 or 1)
    const int m = lane & 15;     // unit-pair index: lane owns hidden units 2m, 2m+1

    __shared__ __align__(16) float sv [WARPS_PER_BLOCK][DDIM]; // stage input vector
    __shared__ __align__(16) float sh1[WARPS_PER_BLOCK][HID];  // hidden 1
    __shared__ __align__(16) float sh2[WARPS_PER_BLOCK][HID];  // hidden 2

    float* svw  = sv [wrp];
    float* sh1w = sh1[wrp];
    float* sh2w = sh2[wrp];

    // ---- weights into registers ----
    // Layer 1: units 2m, 2m+1 over input half g (chunk order rotated for bank
    // disjointness between halves): chunk c1(i) = g*8 + ((i+g)&7)
    u64 w1a[16], w1b[16];
    #pragma unroll
    for (int i = 0; i < 8; ++i) {
        const int c = g * 8 + ((i + g) & 7);
        float4 fa = *(const float4*)(W1 + (2 * m) * DDIM + 4 * c);
        float4 fb = *(const float4*)(W1 + (2 * m + 1) * DDIM + 4 * c);
        w1a[2 * i] = pack2(fa.x, fa.y); w1a[2 * i + 1] = pack2(fa.z, fa.w);
        w1b[2 * i] = pack2(fb.x, fb.y); w1b[2 * i + 1] = pack2(fb.z, fb.w);
    }
    // Layer 2: units 2m, 2m+1 over input half g: chunk c2(i) = g*4 + i
    u64 w2a[8], w2b[8];
    #pragma unroll
    for (int i = 0; i < 4; ++i) {
        const int c = g * 4 + i;
        float4 fa = *(const float4*)(W2 + (2 * m) * HID + 4 * c);
        float4 fb = *(const float4*)(W2 + (2 * m + 1) * HID + 4 * c);
        w2a[2 * i] = pack2(fa.x, fa.y); w2a[2 * i + 1] = pack2(fa.z, fa.w);
        w2b[2 * i] = pack2(fb.x, fb.y); w2b[2 * i + 1] = pack2(fb.z, fb.w);
    }
    // Layer 3: lane owns output coords (2*lane, 2*lane+1), full 32-input dot
    u64 w3ap[HID / 2], w3bp[HID / 2];
    {
        const float2* ra = (const float2*)(W3 + (2 * lane) * HID);
        const float2* rb = (const float2*)(W3 + (2 * lane + 1) * HID);
        #pragma unroll
        for (int j = 0; j < HID / 2; ++j) {
            float2 va = ra[j]; w3ap[j] = pack2(va.x, va.y);
            float2 vb = rb[j]; w3bp[j] = pack2(vb.x, vb.y);
        }
    }
    const float2 b1v = ((const float2*)b1)[m];      // biases for units 2m, 2m+1
    const float2 b2v = ((const float2*)b2)[m];
    const float2 b3v = ((const float2*)b3)[lane];   // rows 2*lane, 2*lane+1

    // f(z) -> k, packed pairs: z/k hold coords (2*lane, 2*lane+1)
    auto evalf = [&](u64 z) -> u64 {
        *(u64*)&svw[2 * lane] = z;              // STS.64
        __syncwarp();
        // ---- layer 1 (half-dot): 8 LDS.128, 32 FFMA2 (2 units x 2 accums) ----
        u64 A0 = 0, A1 = 0, B0 = 0, B1 = 0;
        const ulonglong2* vv = (const ulonglong2*)svw;   // 16B chunks
        #pragma unroll
        for (int i = 0; i < 8; ++i) {
            const int c = g * 8 + ((i + g) & 7);
            ulonglong2 p = vv[c];
            A0 = ffma2(w1a[2 * i],     p.x, A0);
            A1 = ffma2(w1a[2 * i + 1], p.y, A1);
            B0 = ffma2(w1b[2 * i],     p.x, B0);
            B1 = ffma2(w1b[2 * i + 1], p.y, B1);
        }
        float2 sa = unpk(fadd2(A0, A1));
        float2 sb = unpk(fadd2(B0, B1));
        float preA = sa.x + sa.y;
        float preB = sb.x + sb.y;
        preA += __shfl_xor_sync(0xffffffffu, preA, 16);   // combine halves
        preB += __shfl_xor_sync(0xffffffffu, preB, 16);
        float hA = softplus_f(preA + b1v.x);
        float hB = softplus_f(preB + b1v.y);
        if (lane < 16) *(u64*)&sh1w[2 * m] = pack2(hA, hB);  // STS.64
        __syncwarp();
        // ---- layer 2 (half-dot): 4 LDS.128, 16 FFMA2 ----
        u64 C0 = 0, C1 = 0, D0 = 0, D1 = 0;
        const ulonglong2* hh = (const ulonglong2*)sh1w;
        #pragma unroll
        for (int i = 0; i < 4; ++i) {
            ulonglong2 p = hh[g * 4 + i];
            C0 = ffma2(w2a[2 * i],     p.x, C0);
            C1 = ffma2(w2a[2 * i + 1], p.y, C1);
            D0 = ffma2(w2b[2 * i],     p.x, D0);
            D1 = ffma2(w2b[2 * i + 1], p.y, D1);
        }
        float2 sc = unpk(fadd2(C0, C1));
        float2 sd = unpk(fadd2(D0, D1));
        float preC = sc.x + sc.y;
        float preD = sd.x + sd.y;
        preC += __shfl_xor_sync(0xffffffffu, preC, 16);
        preD += __shfl_xor_sync(0xffffffffu, preD, 16);
        float gA = softplus_f(preC + b2v.x);
        float gB = softplus_f(preD + b2v.y);
        if (lane < 16) *(u64*)&sh2w[2 * m] = pack2(gA, gB);
        __syncwarp();
        // ---- layer 3 (full dot): 8 LDS.128, 32 FFMA2 ----
        u64 e0 = 0, e1 = 0, e2 = 0, e3 = 0;   // row 2*lane
        u64 f0 = 0, f1 = 0, f2 = 0, f3 = 0;   // row 2*lane+1
        const ulonglong2* gg = (const ulonglong2*)sh2w;
        #pragma unroll
        for (int j = 0; j < 4; ++j) {
            ulonglong2 p0 = gg[2 * j + 0];
            ulonglong2 p1 = gg[2 * j + 1];
            e0 = ffma2(w3ap[4 * j + 0], p0.x, e0);
            f0 = ffma2(w3bp[4 * j + 0], p0.x, f0);
            e1 = ffma2(w3ap[4 * j + 1], p0.y, e1);
            f1 = ffma2(w3bp[4 * j + 1], p0.y, f1);
            e2 = ffma2(w3ap[4 * j + 2], p1.x, e2);
            f2 = ffma2(w3bp[4 * j + 2], p1.x, f2);
            e3 = ffma2(w3ap[4 * j + 3], p1.y, e3);
            f3 = ffma2(w3bp[4 * j + 3], p1.y, f3);
        }
        float2 se = unpk(fadd2(fadd2(e0, e1), fadd2(e2, e3)));
        float2 sf = unpk(fadd2(fadd2(f0, f1), fadd2(f2, f3)));
        // no trailing syncwarp: next call's barriers cover the WAR hazards
        return pack2((se.x + se.y) + b3v.x, (sf.x + sf.y) + b3v.y);
    };

    // ---- state (packed: coords 2*lane, 2*lane+1) ----
    float2 x0v = ((const float2*)x0s)[sys * (DDIM / 2) + lane];
    u64 yp = pack2(x0v.x, x0v.y);

    const int trajBase = sys * (TRAJ_LEN * DDIM);
    ((float2*)out)[(trajBase >> 1) + lane] = x0v;    // ts[0] row

    const float Tf    = (float)(*Tptr);
    const float stepT = Tf / (float)N_INTERVALS;

    float t = 0.0f;
    float dt = DT0f;
    int   n  = 0;

    u64 k1p = evalf(yp);   // FSAL seed

    for (int iv = 1; iv <= N_INTERVALS; ++iv) {
        const float t_target = (iv == N_INTERVALS) ? Tf : stepT * (float)iv;

        for (int it = 0; it < MAX_INNER; ++it) {
            float remaining = t_target - t;
            if (remaining <= 1e-12f) break;
            float h = fminf(dt, fmaxf(remaining, 0.0f));
            u64 hp = dup2(h);

            // stage 2
            u64 s = fmul2(dup2(A21f), k1p);
            u64 k2p = evalf(ffma2(hp, s, yp));
            // stage 3
            s = ffma2(dup2(A32f), k2p, fmul2(dup2(A31f), k1p));
            u64 k3p = evalf(ffma2(hp, s, yp));
            // stage 4
            s = ffma2(dup2(A42f), k2p, fmul2(dup2(A41f), k1p));
            s = ffma2(dup2(A43f), k3p, s);
            u64 k4p = evalf(ffma2(hp, s, yp));
            // stage 5
            s = ffma2(dup2(A52f), k2p, fmul2(dup2(A51f), k1p));
            s = ffma2(dup2(A53f), k3p, s);
            s = ffma2(dup2(A54f), k4p, s);
            u64 k5p = evalf(ffma2(hp, s, yp));
            // stage 6
            s = ffma2(dup2(A62f), k2p, fmul2(dup2(A61f), k1p));
            s = ffma2(dup2(A63f), k3p, s);
            s = ffma2(dup2(A64f), k4p, s);
            s = ffma2(dup2(A65f), k5p, s);
            u64 k6p = evalf(ffma2(hp, s, yp));
            // y5
            s = ffma2(dup2(B2f), k2p, fmul2(dup2(B1f), k1p));
            s = ffma2(dup2(B3f), k3p, s);
            s = ffma2(dup2(B4f), k4p, s);
            s = ffma2(dup2(B5f), k5p, s);
            s = ffma2(dup2(B6f), k6p, s);
            u64 y5p = ffma2(hp, s, yp);
            // stage 7 (FSAL)
            u64 k7p = evalf(y5p);
            // error estimate
            s = ffma2(dup2(E2f), k2p, fmul2(dup2(E1f), k1p));
            s = ffma2(dup2(E3f), k3p, s);
            s = ffma2(dup2(E4f), k4p, s);
            s = ffma2(dup2(E5f), k5p, s);
            s = ffma2(dup2(E6f), k6p, s);
            s = ffma2(dup2(E7f), k7p, s);
            float2 ev  = unpk(fmul2(hp, s));
            float2 yv  = unpk(yp);
            float2 y5v = unpk(y5p);

            float scl = fmaf(RTOLf, fmaxf(fabsf(yv.x), fabsf(y5v.x)), ATOLf);
            float sch = fmaf(RTOLf, fmaxf(fabsf(yv.y), fabsf(y5v.y)), ATOLf);
            float ql = __fdividef(ev.x, scl);
            float qh = __fdividef(ev.y, sch);
            float local = ql * ql + qh * qh;
            #pragma unroll
            for (int o = 16; o > 0; o >>= 1)
                local += __shfl_xor_sync(0xffffffffu, local, o);

            // enorm = max(sqrt(local/64), 1e-10); accept <=> local <= 64
            // fac = 0.9 * enorm^-0.2 = 0.9 * exp2(-0.1*(log2(local) - 6)), sqrt-free
            bool accept = (local <= 64.0f);
            float lg = __log2f(fmaxf(local, 4.096e-18f)) - 6.0f;  // floor == (1e-10)^2*64
            float fac = 0.9f * exp2f(-0.1f * lg);
            fac = fminf(fmaxf(fac, 0.1f), 5.0f);

            if (accept) {
                t = t + h;
                yp  = y5p;
                k1p = k7p;   // FSAL
            }
            dt = fmaxf(h * fac, 1e-8f);
            n += 1;
        }

        float2 yv = unpk(yp);
        ((float2*)out)[((trajBase + iv * DDIM) >> 1) + lane] = yv;
    }

    if (lane == 0)
        atomicAdd(&out[nIdx], (float)n);   // integer-valued, exact
}

// zero the (poisoned) tail of the output buffer that holds the step-count sum
__global__ void init_tail_kernel(float* __restrict__ out, int start, int total) {
    int i = start + blockIdx.x * blockDim.x + threadIdx.x;
    if (i < total) out[i] = 0.0f;
}

extern "C" void kernel_launch(void* const* d_in, const int* in_sizes, int n_in,
                              void* d_out, int out_size) {
    const float* x0s = (const float*)d_in[0];
    const float* W1  = (const float*)d_in[1];
    const float* b1  = (const float*)d_in[2];
    const float* W2  = (const float*)d_in[3];
    const float* b2  = (const float*)d_in[4];
    const float* W3  = (const float*)d_in[5];
    const float* b3  = (const float*)d_in[6];
    const int*   Tp  = (const int*)d_in[7];

    const int B = in_sizes[0] / DDIM;
    float* out = (float*)d_out;

    int trajElems = B * TRAJ_LEN * DDIM;
    if (trajElems >= out_size) trajElems = out_size - 1;  // safety
    const int nIdx = trajElems;

    const int tail = out_size - trajElems;
    init_tail_kernel<<<(tail + 255) / 256, 256>>>(out, trajElems, out_size);

    const int blocks = (B + WARPS_PER_BLOCK - 1) / WARPS_PER_BLOCK;
    neural_ode_kernel<<<blocks, THREADS_PER_BLOCK>>>(
        x0s, W1, b1, W2, b2, W3, b3, Tp, out, B, nIdx);
}

// round 10
// speedup vs baseline: 1.5139x; 1.1197x over previous
#include <cuda_runtime.h>

typedef unsigned long long u64;

// ---------------------------------------------------------------------------
// packed f32x2 helpers (Blackwell FFMA2 path)
// ---------------------------------------------------------------------------
__device__ __forceinline__ u64 ffma2(u64 a, u64 b, u64 c) {
    u64 d; asm("fma.rn.f32x2 %0, %1, %2, %3;" : "=l"(d) : "l"(a), "l"(b), "l"(c)); return d;
}
__device__ __forceinline__ u64 fadd2(u64 a, u64 b) {
    u64 d; asm("add.rn.f32x2 %0, %1, %2;" : "=l"(d) : "l"(a), "l"(b)); return d;
}
__device__ __forceinline__ u64 fmul2(u64 a, u64 b) {
    u64 d; asm("mul.rn.f32x2 %0, %1, %2;" : "=l"(d) : "l"(a), "l"(b)); return d;
}
__device__ __forceinline__ u64 pack2(float lo, float hi) {
    u64 d; asm("mov.b64 %0, {%1, %2};" : "=l"(d) : "f"(lo), "f"(hi)); return d;
}
__device__ __forceinline__ float2 unpk(u64 v) {
    float2 r; asm("mov.b64 {%0, %1}, %2;" : "=f"(r.x), "=f"(r.y) : "l"(v)); return r;
}
__device__ __forceinline__ u64 dup2(float c) { return pack2(c, c); }

// ---------------------------------------------------------------------------
// Tsit5 constants
// ---------------------------------------------------------------------------
#define A21f 0.161f
#define A31f (-0.008480655492356989f)
#define A32f 0.335480655492357f
#define A41f 2.8971530571054935f
#define A42f (-6.359448489975075f)
#define A43f 4.3622954328695815f
#define A51f 5.325864828439257f
#define A52f (-11.748883564062828f)
#define A53f 7.4955393428898365f
#define A54f (-0.09249506636175525f)
#define A61f 5.86145544294642f
#define A62f (-12.92096931784711f)
#define A63f 8.159367898576159f
#define A64f (-0.071584973281401f)
#define A65f (-0.028269050394068383f)
#define B1f 0.09646076681806523f
#define B2f 0.01f
#define B3f 0.4798896504144996f
#define B4f 1.379008574103742f
#define B5f (-3.290069515436081f)
#define B6f 2.324710524099774f
#define E1f (-0.00178001105222577714f)
#define E2f (-0.0008164344596567469f)
#define E3f 0.007880878010261995f
#define E4f (-0.1447110071732629f)
#define E5f 0.5823571654525552f
#define E6f (-0.45808210592918697f)
#define E7f 0.015151515151515152f

#define RTOLf 1e-3f
#define ATOLf 1e-6f
#define DT0f  1e-3f

#define DDIM 64
#define HID  32
#define TRAJ_LEN 11
#define N_INTERVALS 10
#define MAX_INNER 64

#define WARPS_PER_BLOCK 4
#define THREADS_PER_BLOCK (WARPS_PER_BLOCK * 32)
#define PERSISTENT_BLOCKS 304   // 2 blocks/SM x 152 SMs (GB300)

// global work-stealing counter (reset by init kernel every launch)
__device__ int g_sys_counter;

// fast softplus: max(x,0) + log(1 + exp(-|x|)) with MUFU exp/log
__device__ __forceinline__ float softplus_f(float x) {
    return fmaxf(x, 0.0f) + __logf(1.0f + __expf(-fabsf(x)));
}

__global__ void __launch_bounds__(THREADS_PER_BLOCK, 2)
neural_ode_kernel(const float* __restrict__ x0s,
                  const float* __restrict__ W1, const float* __restrict__ b1,
                  const float* __restrict__ W2, const float* __restrict__ b2,
                  const float* __restrict__ W3, const float* __restrict__ b3,
                  const int* __restrict__ Tptr,
                  float* __restrict__ out, int B, int nIdx)
{
    const int lane = threadIdx.x & 31;
    const int wrp  = threadIdx.x >> 5;

    const int g = lane >> 4;     // input-half group (0 or 1)
    const int m = lane & 15;     // unit-pair index: lane owns hidden units 2m, 2m+1

    __shared__ __align__(16) float sv [WARPS_PER_BLOCK][DDIM]; // stage input vector
    __shared__ __align__(16) float sh1[WARPS_PER_BLOCK][HID];  // hidden 1
    __shared__ __align__(16) float sh2[WARPS_PER_BLOCK][HID];  // hidden 2

    float* svw  = sv [wrp];
    float* sh1w = sh1[wrp];
    float* sh2w = sh2[wrp];

    // ---- weights into registers, ONCE per persistent warp ----
    // Layer 1: units 2m, 2m+1 over input half g (rotated chunk order)
    u64 w1a[16], w1b[16];
    #pragma unroll
    for (int i = 0; i < 8; ++i) {
        const int c = g * 8 + ((i + g) & 7);
        float4 fa = *(const float4*)(W1 + (2 * m) * DDIM + 4 * c);
        float4 fb = *(const float4*)(W1 + (2 * m + 1) * DDIM + 4 * c);
        w1a[2 * i] = pack2(fa.x, fa.y); w1a[2 * i + 1] = pack2(fa.z, fa.w);
        w1b[2 * i] = pack2(fb.x, fb.y); w1b[2 * i + 1] = pack2(fb.z, fb.w);
    }
    // Layer 2: units 2m, 2m+1 over input half g
    u64 w2a[8], w2b[8];
    #pragma unroll
    for (int i = 0; i < 4; ++i) {
        const int c = g * 4 + i;
        float4 fa = *(const float4*)(W2 + (2 * m) * HID + 4 * c);
        float4 fb = *(const float4*)(W2 + (2 * m + 1) * HID + 4 * c);
        w2a[2 * i] = pack2(fa.x, fa.y); w2a[2 * i + 1] = pack2(fa.z, fa.w);
        w2b[2 * i] = pack2(fb.x, fb.y); w2b[2 * i + 1] = pack2(fb.z, fb.w);
    }
    // Layer 3: lane owns output coords (2*lane, 2*lane+1), full 32-input dot
    u64 w3ap[HID / 2], w3bp[HID / 2];
    {
        const float2* ra = (const float2*)(W3 + (2 * lane) * HID);
        const float2* rb = (const float2*)(W3 + (2 * lane + 1) * HID);
        #pragma unroll
        for (int j = 0; j < HID / 2; ++j) {
            float2 va = ra[j]; w3ap[j] = pack2(va.x, va.y);
            float2 vb = rb[j]; w3bp[j] = pack2(vb.x, vb.y);
        }
    }
    const float2 b1v = ((const float2*)b1)[m];      // biases for units 2m, 2m+1
    const float2 b2v = ((const float2*)b2)[m];
    const float2 b3v = ((const float2*)b3)[lane];   // rows 2*lane, 2*lane+1

    const float Tf    = (float)(*Tptr);
    const float stepT = Tf / (float)N_INTERVALS;

    // f(z) -> k, packed pairs: z/k hold coords (2*lane, 2*lane+1)
    auto evalf = [&](u64 z) -> u64 {
        *(u64*)&svw[2 * lane] = z;              // STS.64
        __syncwarp();
        // ---- layer 1 (half-dot): 8 LDS.128, 32 FFMA2 ----
        u64 A0 = 0, A1 = 0, B0 = 0, B1 = 0;
        const ulonglong2* vv = (const ulonglong2*)svw;
        #pragma unroll
        for (int i = 0; i < 8; ++i) {
            const int c = g * 8 + ((i + g) & 7);
            ulonglong2 p = vv[c];
            A0 = ffma2(w1a[2 * i],     p.x, A0);
            A1 = ffma2(w1a[2 * i + 1], p.y, A1);
            B0 = ffma2(w1b[2 * i],     p.x, B0);
            B1 = ffma2(w1b[2 * i + 1], p.y, B1);
        }
        float2 sa = unpk(fadd2(A0, A1));
        float2 sb = unpk(fadd2(B0, B1));
        float preA = sa.x + sa.y;
        float preB = sb.x + sb.y;
        preA += __shfl_xor_sync(0xffffffffu, preA, 16);   // combine halves
        preB += __shfl_xor_sync(0xffffffffu, preB, 16);
        float hA = softplus_f(preA + b1v.x);
        float hB = softplus_f(preB + b1v.y);
        if (lane < 16) *(u64*)&sh1w[2 * m] = pack2(hA, hB);
        __syncwarp();
        // ---- layer 2 (half-dot): 4 LDS.128, 16 FFMA2 ----
        u64 C0 = 0, C1 = 0, D0 = 0, D1 = 0;
        const ulonglong2* hh = (const ulonglong2*)sh1w;
        #pragma unroll
        for (int i = 0; i < 4; ++i) {
            ulonglong2 p = hh[g * 4 + i];
            C0 = ffma2(w2a[2 * i],     p.x, C0);
            C1 = ffma2(w2a[2 * i + 1], p.y, C1);
            D0 = ffma2(w2b[2 * i],     p.x, D0);
            D1 = ffma2(w2b[2 * i + 1], p.y, D1);
        }
        float2 sc = unpk(fadd2(C0, C1));
        float2 sd = unpk(fadd2(D0, D1));
        float preC = sc.x + sc.y;
        float preD = sd.x + sd.y;
        preC += __shfl_xor_sync(0xffffffffu, preC, 16);
        preD += __shfl_xor_sync(0xffffffffu, preD, 16);
        float gA = softplus_f(preC + b2v.x);
        float gB = softplus_f(preD + b2v.y);
        if (lane < 16) *(u64*)&sh2w[2 * m] = pack2(gA, gB);
        __syncwarp();
        // ---- layer 3 (full dot): 8 LDS.128, 32 FFMA2 ----
        u64 e0 = 0, e1 = 0, e2 = 0, e3 = 0;   // row 2*lane
        u64 f0 = 0, f1 = 0, f2 = 0, f3 = 0;   // row 2*lane+1
        const ulonglong2* gg = (const ulonglong2*)sh2w;
        #pragma unroll
        for (int j = 0; j < 4; ++j) {
            ulonglong2 p0 = gg[2 * j + 0];
            ulonglong2 p1 = gg[2 * j + 1];
            e0 = ffma2(w3ap[4 * j + 0], p0.x, e0);
            f0 = ffma2(w3bp[4 * j + 0], p0.x, f0);
            e1 = ffma2(w3ap[4 * j + 1], p0.y, e1);
            f1 = ffma2(w3bp[4 * j + 1], p0.y, f1);
            e2 = ffma2(w3ap[4 * j + 2], p1.x, e2);
            f2 = ffma2(w3bp[4 * j + 2], p1.x, f2);
            e3 = ffma2(w3ap[4 * j + 3], p1.y, e3);
            f3 = ffma2(w3bp[4 * j + 3], p1.y, f3);
        }
        float2 se = unpk(fadd2(fadd2(e0, e1), fadd2(e2, e3)));
        float2 sf = unpk(fadd2(fadd2(f0, f1), fadd2(f2, f3)));
        // no trailing syncwarp: next call's barriers cover the WAR hazards
        return pack2((se.x + se.y) + b3v.x, (sf.x + sf.y) + b3v.y);
    };

    // =======================================================================
    // persistent loop: steal system IDs until exhausted
    // =======================================================================
    for (;;) {
        int sys;
        if (lane == 0) sys = atomicAdd(&g_sys_counter, 1);
        sys = __shfl_sync(0xffffffffu, sys, 0);
        if (sys >= B) break;

        // ---- per-system state (packed: coords 2*lane, 2*lane+1) ----
        float2 x0v = ((const float2*)x0s)[sys * (DDIM / 2) + lane];
        u64 yp = pack2(x0v.x, x0v.y);

        const int trajBase = sys * (TRAJ_LEN * DDIM);
        ((float2*)out)[(trajBase >> 1) + lane] = x0v;    // ts[0] row

        float t = 0.0f;
        float dt = DT0f;
        int   n  = 0;

        u64 k1p = evalf(yp);   // FSAL seed

        for (int iv = 1; iv <= N_INTERVALS; ++iv) {
            const float t_target = (iv == N_INTERVALS) ? Tf : stepT * (float)iv;

            for (int it = 0; it < MAX_INNER; ++it) {
                float remaining = t_target - t;
                if (remaining <= 1e-12f) break;
                float h = fminf(dt, fmaxf(remaining, 0.0f));
                u64 hp = dup2(h);

                // stage 2
                u64 s = fmul2(dup2(A21f), k1p);
                u64 k2p = evalf(ffma2(hp, s, yp));
                // stage 3
                s = ffma2(dup2(A32f), k2p, fmul2(dup2(A31f), k1p));
                u64 k3p = evalf(ffma2(hp, s, yp));
                // stage 4
                s = ffma2(dup2(A42f), k2p, fmul2(dup2(A41f), k1p));
                s = ffma2(dup2(A43f), k3p, s);
                u64 k4p = evalf(ffma2(hp, s, yp));
                // stage 5
                s = ffma2(dup2(A52f), k2p, fmul2(dup2(A51f), k1p));
                s = ffma2(dup2(A53f), k3p, s);
                s = ffma2(dup2(A54f), k4p, s);
                u64 k5p = evalf(ffma2(hp, s, yp));
                // stage 6
                s = ffma2(dup2(A62f), k2p, fmul2(dup2(A61f), k1p));
                s = ffma2(dup2(A63f), k3p, s);
                s = ffma2(dup2(A64f), k4p, s);
                s = ffma2(dup2(A65f), k5p, s);
                u64 k6p = evalf(ffma2(hp, s, yp));
                // y5
                s = ffma2(dup2(B2f), k2p, fmul2(dup2(B1f), k1p));
                s = ffma2(dup2(B3f), k3p, s);
                s = ffma2(dup2(B4f), k4p, s);
                s = ffma2(dup2(B5f), k5p, s);
                s = ffma2(dup2(B6f), k6p, s);
                u64 y5p = ffma2(hp, s, yp);
                // stage 7 (FSAL)
                u64 k7p = evalf(y5p);
                // error estimate
                s = ffma2(dup2(E2f), k2p, fmul2(dup2(E1f), k1p));
                s = ffma2(dup2(E3f), k3p, s);
                s = ffma2(dup2(E4f), k4p, s);
                s = ffma2(dup2(E5f), k5p, s);
                s = ffma2(dup2(E6f), k6p, s);
                s = ffma2(dup2(E7f), k7p, s);
                float2 ev  = unpk(fmul2(hp, s));
                float2 yv  = unpk(yp);
                float2 y5v = unpk(y5p);

                float scl = fmaf(RTOLf, fmaxf(fabsf(yv.x), fabsf(y5v.x)), ATOLf);
                float sch = fmaf(RTOLf, fmaxf(fabsf(yv.y), fabsf(y5v.y)), ATOLf);
                float ql = __fdividef(ev.x, scl);
                float qh = __fdividef(ev.y, sch);
                float local = ql * ql + qh * qh;
                #pragma unroll
                for (int o = 16; o > 0; o >>= 1)
                    local += __shfl_xor_sync(0xffffffffu, local, o);

                // enorm = max(sqrt(local/64), 1e-10); accept <=> local <= 64
                // fac = 0.9 * exp2(-0.1*(log2(local) - 6)), sqrt-free
                bool accept = (local <= 64.0f);
                float lg = __log2f(fmaxf(local, 4.096e-18f)) - 6.0f;
                float fac = 0.9f * exp2f(-0.1f * lg);
                fac = fminf(fmaxf(fac, 0.1f), 5.0f);

                if (accept) {
                    t = t + h;
                    yp  = y5p;
                    k1p = k7p;   // FSAL
                }
                dt = fmaxf(h * fac, 1e-8f);
                n += 1;
            }

            float2 yv = unpk(yp);
            ((float2*)out)[((trajBase + iv * DDIM) >> 1) + lane] = yv;
        }

        if (lane == 0)
            atomicAdd(&out[nIdx], (float)n);   // integer-valued, exact
    }
}

// zero the poisoned tail of the output buffer AND the work-stealing counter
__global__ void init_kernel(float* __restrict__ out, int start, int total) {
    if (blockIdx.x == 0 && threadIdx.x == 0) g_sys_counter = 0;
    int i = start + blockIdx.x * blockDim.x + threadIdx.x;
    if (i < total) out[i] = 0.0f;
}

extern "C" void kernel_launch(void* const* d_in, const int* in_sizes, int n_in,
                              void* d_out, int out_size) {
    const float* x0s = (const float*)d_in[0];
    const float* W1  = (const float*)d_in[1];
    const float* b1  = (const float*)d_in[2];
    const float* W2  = (const float*)d_in[3];
    const float* b2  = (const float*)d_in[4];
    const float* W3  = (const float*)d_in[5];
    const float* b3  = (const float*)d_in[6];
    const int*   Tp  = (const int*)d_in[7];

    const int B = in_sizes[0] / DDIM;
    float* out = (float*)d_out;

    int trajElems = B * TRAJ_LEN * DDIM;
    if (trajElems >= out_size) trajElems = out_size - 1;  // safety
    const int nIdx = trajElems;

    const int tail = out_size - trajElems;
    init_kernel<<<(tail + 255) / 256 > 0 ? (tail + 255) / 256 : 1, 256>>>(out, trajElems, out_size);

    neural_ode_kernel<<<PERSISTENT_BLOCKS, THREADS_PER_BLOCK>>>(
        x0s, W1, b1, W2, b2, W3, b3, Tp, out, B, nIdx);
}